// round 13
// baseline (speedup 1.0000x reference)
#include <cuda_runtime.h>
#include <cstdint>

// x (512,1,64,64) f32, weights (4,4,3) f32 -> out (512,12,31,31) f32
#define B_    512
#define H_    64
#define W_    64
#define HO_   31
#define WO_   31
#define NK_   4
#define LL_   (HO_ * WO_)            // 961
#define NWARP_ (B_ * HO_)            // 15872 warps, one per (b, oh)
#define WPB_   8                     // 256-thread blocks
#define NBLK_  (NWARP_ / WPB_)       // 1984 exact

#define TSTRIDE_ 68                  // smem row stride (floats): pad kills conflicts

typedef unsigned long long u64;

__device__ __forceinline__ float frcp_approx(float x) {
    float r;
    asm("rcp.approx.f32 %0, %1;" : "=f"(r) : "f"(x));
    return r;
}
// Packed fp32x2 (sm_103a FFMA2/FMUL2/FADD2 — only reachable via explicit PTX)
__device__ __forceinline__ u64 mul2(u64 a, u64 b) {
    u64 r; asm("mul.rn.f32x2 %0, %1, %2;" : "=l"(r) : "l"(a), "l"(b)); return r;
}
__device__ __forceinline__ u64 add2(u64 a, u64 b) {
    u64 r; asm("add.rn.f32x2 %0, %1, %2;" : "=l"(r) : "l"(a), "l"(b)); return r;
}
__device__ __forceinline__ u64 fma2(u64 a, u64 b, u64 c) {
    u64 r; asm("fma.rn.f32x2 %0, %1, %2, %3;" : "=l"(r) : "l"(a), "l"(b), "l"(c)); return r;
}
__device__ __forceinline__ float2 unpk(u64 a) {
    float2 f; asm("mov.b64 {%0, %1}, %2;" : "=f"(f.x), "=f"(f.y) : "l"(a)); return f;
}

__global__ __launch_bounds__(256) void qconv_kernel(const float* __restrict__ x,
                                                    const float* __restrict__ w,
                                                    float* __restrict__ out) {
    // Coefs: reduced-density-matrix algebra — only weights[k][0]=(th,ph,om) matter.
    // e_a = alpha_a * d + beta_a * cc.
    __shared__ float2 sc2[12];
    __shared__ float tile[WPB_][4][TSTRIDE_];

    if (threadIdx.x < NK_) {
        int k = threadIdx.x;
        float th = w[k * 12 + 0];
        float ph = w[k * 12 + 1];
        float om = w[k * 12 + 2];
        float st, ct, sp, cp, spo, cpo, smo, cmo, so, co;
        __sincosf(th, &st, &ct);
        __sincosf(ph, &sp, &cp);
        __sincosf(ph + om, &spo, &cpo);
        __sincosf(om - ph, &smo, &cmo);
        __sincosf(om, &so, &co);
        float c2 = 0.5f * (1.0f + ct);
        float s2 = 0.5f * (1.0f - ct);
        sc2[k * 3 + 0] = make_float2(st * cp, 2.0f * (c2 * cpo - s2 * cmo));
        sc2[k * 3 + 1] = make_float2(st * sp, 2.0f * (c2 * spo + s2 * smo));
        sc2[k * 3 + 2] = make_float2(ct, -2.0f * st * co);
    }
    __syncthreads();

    int wslot = threadIdx.x >> 5;
    int lane  = threadIdx.x & 31;
    int Wg    = blockIdx.x * WPB_ + wslot;   // global warp id = (b, oh)
    int b  = Wg / HO_;
    int oh = Wg - b * HO_;

    // Warp cooperative load: 4 rows x 64 cols strip, every float loaded once.
    const float* base = x + (size_t)(b * H_ + 2 * oh) * W_;
#pragma unroll
    for (int j = 0; j < 2; j++) {
        int idx = lane + 32 * j;             // 0..63
        int r   = idx >> 4;
        int c4  = idx & 15;
        float4 v = *reinterpret_cast<const float4*>(base + r * W_ + c4 * 4);
        *reinterpret_cast<float4*>(&tile[wslot][r][c4 * 4]) = v;
    }
    __syncwarp();

    // No lane<31 branch: lane 31 computes on in-bounds (padded) smem, stores predicated.
    // Window for patch ow=lane: rows 0..3, cols 2*lane .. 2*lane+3 (8B-aligned pairs).
    u64 pa0 = *reinterpret_cast<const u64*>(&tile[wslot][0][2 * lane]);
    u64 pb0 = *reinterpret_cast<const u64*>(&tile[wslot][0][2 * lane + 2]);
    u64 pa1 = *reinterpret_cast<const u64*>(&tile[wslot][1][2 * lane]);
    u64 pb1 = *reinterpret_cast<const u64*>(&tile[wslot][1][2 * lane + 2]);
    u64 pa2 = *reinterpret_cast<const u64*>(&tile[wslot][2][2 * lane]);
    u64 pb2 = *reinterpret_cast<const u64*>(&tile[wslot][2][2 * lane + 2]);
    u64 pa3 = *reinterpret_cast<const u64*>(&tile[wslot][3][2 * lane]);
    u64 pb3 = *reinterpret_cast<const u64*>(&tile[wslot][3][2 * lane + 2]);

    // CNOT-ring folded to index algebra (column signs +,-,-,+), packed per col-pair:
    //   A = v0^2+v2^2, B = v1^2+v3^2, C = v0*v3 + v1*v2  (off-diag partner i^12)
    u64 A01 = fma2(pa2, pa2, mul2(pa0, pa0));
    u64 B01 = fma2(pa3, pa3, mul2(pa1, pa1));
    u64 A23 = fma2(pb2, pb2, mul2(pb0, pb0));
    u64 B23 = fma2(pb3, pb3, mul2(pb1, pb1));
    u64 C01 = fma2(pa0, pa3, mul2(pa1, pa2));
    u64 C23 = fma2(pb0, pb3, mul2(pb1, pb2));

    const u64 SGN2 = 0x8000000080000000ULL;  // packed sign-flip (no sub.f32x2 needed)
    u64 S   = add2(add2(A01, B01), add2(A23, B23));
    u64 D01 = add2(A01, B01 ^ SGN2);
    u64 D23 = add2(A23, B23 ^ SGN2);
    u64 Cs  = add2(C01, C23);

    float2 s2v = unpk(S);
    float2 d01 = unpk(D01);
    float2 d23 = unpk(D23);
    float2 csv = unpk(Cs);

    float nrm = s2v.x + s2v.y;
    float d   = (d01.x - d01.y) - (d23.x - d23.y);
    float cc  = csv.x + csv.y;

    float inv = frcp_approx(fmaxf(nrm, 1e-30f));
    d  *= inv;
    cc *= inv;

    // out[b, ch, oh, ow]; lanes 0..30 -> 31 consecutive floats per channel
    float* o = out + (size_t)b * (12 * LL_) + oh * WO_ + lane;
    bool act = (lane < WO_);
#pragma unroll
    for (int ch = 0; ch < 12; ch++) {
        float2 ab = sc2[ch];
        float e = fmaf(ab.x, d, ab.y * cc);
        if (act) o[(size_t)ch * LL_] = e;    // predicated STG, no branch
    }
}

extern "C" void kernel_launch(void* const* d_in, const int* in_sizes, int n_in,
                              void* d_out, int out_size) {
    const float* x = (const float*)d_in[0];
    const float* w = (const float*)d_in[1];
    if (n_in >= 2 && in_sizes[0] == NK_ * 4 * 3) {  // defensive input-order swap
        x = (const float*)d_in[1];
        w = (const float*)d_in[0];
    }
    qconv_kernel<<<NBLK_, 256>>>(x, w, (float*)d_out);
}